// round 1
// baseline (speedup 1.0000x reference)
#include <cuda_runtime.h>
#include <math.h>

#define TLEN  32000
#define BATCH 8
#define RES   32
#define SKIPC 32
#define TT    128   // time samples per block

// ---------------- device scratch (static; no allocations allowed) ----------
__device__ float g_h0[BATCH * RES * TLEN];
__device__ float g_h1[BATCH * RES * TLEN];
__device__ float g_skip[BATCH * SKIPC * TLEN];
__device__ float g_ts[BATCH * SKIPC * TLEN];
__device__ float g_p2[BATCH * 16 * TLEN];
__device__ float g_p3[BATCH * 8 * TLEN];
__device__ float g_p4[BATCH * 1 * TLEN];

// ---------------- front conv: x[B,1,T] -> h0[B,32,T]; also zero skip -------
__global__ __launch_bounds__(TT) void k_front(const float* __restrict__ x,
                                              const float* __restrict__ w) {
    int b = blockIdx.y;
    int t = blockIdx.x * TT + threadIdx.x;
    if (t >= TLEN) return;
    const float* xb = x + b * TLEN;
    float x0 = xb[t];
    float x1 = (t >= 1) ? xb[t - 1] : 0.f;
    float x2 = (t >= 2) ? xb[t - 2] : 0.f;
#pragma unroll
    for (int oc = 0; oc < RES; oc++) {
        // causal: w[oc,0,k] pairs with x[t - (2-k)]
        float v = fmaf(w[oc * 3 + 0], x2,
                  fmaf(w[oc * 3 + 1], x1,
                       w[oc * 3 + 2] * x0));
        g_h0[(b * RES + oc) * TLEN + t] = v;
        g_skip[(b * SKIPC + oc) * TLEN + t] = 0.f;
    }
}

// ---------------- residual layer ------------------------------------------
// y = dilated conv(hin, w1)[64]; g = tanh(y0:32)*sigmoid(y32:64)
// z = g @ w2 (64); hout = hin + z[0:32]; skip += z[32:64]
__global__ __launch_bounds__(TT) void k_layer(const float* __restrict__ hin,
                                              float* __restrict__ hout,
                                              const float* __restrict__ w1,  // [64][32][3]
                                              const float* __restrict__ w2,  // [64][32]
                                              int d) {
    __shared__ float w1s[3][RES][64];   // [k][ic][oc] -> oc contiguous for float4
    __shared__ float w2s[RES][64];      // [ic][oc]

    int tid = threadIdx.x;
    for (int i = tid; i < 64 * RES * 3; i += TT) {
        int oc = i / 96, r = i % 96, ic = r / 3, k = r % 3;
        w1s[k][ic][oc] = w1[i];
    }
    for (int i = tid; i < 64 * RES; i += TT) {
        int oc = i / RES, ic = i % RES;
        w2s[ic][oc] = w2[i];
    }
    __syncthreads();

    int b = blockIdx.y;
    int t = blockIdx.x * TT + tid;
    if (t >= TLEN) return;

    const float* hb = hin + b * RES * TLEN;

    float acc[64];
#pragma unroll
    for (int o = 0; o < 64; o++) acc[o] = 0.f;

#pragma unroll
    for (int k = 0; k < 3; k++) {
        int tt = t - (2 - k) * d;
        if (tt >= 0) {
#pragma unroll 4
            for (int ic = 0; ic < RES; ic++) {
                float v = hb[ic * TLEN + tt];
                const float4* wv = reinterpret_cast<const float4*>(&w1s[k][ic][0]);
#pragma unroll
                for (int o4 = 0; o4 < 16; o4++) {
                    float4 wq = wv[o4];
                    acc[o4 * 4 + 0] = fmaf(v, wq.x, acc[o4 * 4 + 0]);
                    acc[o4 * 4 + 1] = fmaf(v, wq.y, acc[o4 * 4 + 1]);
                    acc[o4 * 4 + 2] = fmaf(v, wq.z, acc[o4 * 4 + 2]);
                    acc[o4 * 4 + 3] = fmaf(v, wq.w, acc[o4 * 4 + 3]);
                }
            }
        }
    }

    // gating
    float g[RES];
#pragma unroll
    for (int c = 0; c < RES; c++) {
        float s = 1.f / (1.f + __expf(-acc[c + 32]));
        g[c] = tanhf(acc[c]) * s;
    }

    // 1x1 conv
    float z[64];
#pragma unroll
    for (int o = 0; o < 64; o++) z[o] = 0.f;
#pragma unroll 4
    for (int ic = 0; ic < RES; ic++) {
        float v = g[ic];
        const float4* wv = reinterpret_cast<const float4*>(&w2s[ic][0]);
#pragma unroll
        for (int o4 = 0; o4 < 16; o4++) {
            float4 wq = wv[o4];
            z[o4 * 4 + 0] = fmaf(v, wq.x, z[o4 * 4 + 0]);
            z[o4 * 4 + 1] = fmaf(v, wq.y, z[o4 * 4 + 1]);
            z[o4 * 4 + 2] = fmaf(v, wq.z, z[o4 * 4 + 2]);
            z[o4 * 4 + 3] = fmaf(v, wq.w, z[o4 * 4 + 3]);
        }
    }

    float* hob = hout + b * RES * TLEN;
    float* skb = g_skip + b * SKIPC * TLEN;
#pragma unroll
    for (int c = 0; c < RES; c++)
        hob[c * TLEN + t] = hb[c * TLEN + t] + z[c];
#pragma unroll
    for (int c = 0; c < SKIPC; c++)
        skb[c * TLEN + t] += z[32 + c];
}

// ---------------- tanh over skip ------------------------------------------
__global__ __launch_bounds__(TT) void k_tanhskip() {
    int b = blockIdx.y;
    int t = blockIdx.x * TT + threadIdx.x;
    if (t >= TLEN) return;
#pragma unroll
    for (int c = 0; c < SKIPC; c++) {
        int idx = (b * SKIPC + c) * TLEN + t;
        g_ts[idx] = tanhf(g_skip[idx]);
    }
}

// ---------------- generic causal k=3 conv + tanh --------------------------
template <int IC, int OC>
__global__ __launch_bounds__(TT) void k_conv3tanh(const float* __restrict__ in,
                                                  float* __restrict__ out,
                                                  const float* __restrict__ w) {
    __shared__ float ws[3][IC][OC];
    int tid = threadIdx.x;
    for (int i = tid; i < OC * IC * 3; i += TT) {
        int oc = i / (IC * 3), r = i % (IC * 3), ic = r / 3, k = r % 3;
        ws[k][ic][oc] = w[i];
    }
    __syncthreads();

    int b = blockIdx.y;
    int t = blockIdx.x * TT + tid;
    if (t >= TLEN) return;
    const float* ib = in + b * IC * TLEN;

    float acc[OC];
#pragma unroll
    for (int o = 0; o < OC; o++) acc[o] = 0.f;

#pragma unroll
    for (int k = 0; k < 3; k++) {
        int tt = t - (2 - k);
        if (tt >= 0) {
#pragma unroll
            for (int ic = 0; ic < IC; ic++) {
                float v = ib[ic * TLEN + tt];
#pragma unroll
                for (int o = 0; o < OC; o++)
                    acc[o] = fmaf(v, ws[k][ic][o], acc[o]);
            }
        }
    }
    float* ob = out + b * OC * TLEN;
#pragma unroll
    for (int o = 0; o < OC; o++)
        ob[o * TLEN + t] = tanhf(acc[o]);
}

// ---------------- Volterra head -------------------------------------------
__global__ __launch_bounds__(TT) void k_vnn(const float* __restrict__ w1,   // [16]
                                            const float* __restrict__ w2,   // [6][16]
                                            float* __restrict__ out) {
    int b = blockIdx.y;
    int t = blockIdx.x * TT + threadIdx.x;
    if (t >= TLEN) return;
    const float* pb = g_p4 + b * TLEN;

    float pv[16];
#pragma unroll
    for (int k = 0; k < 16; k++) {
        int tt = t - (15 - k);
        pv[k] = (tt >= 0) ? pb[tt] : 0.f;
    }
    float lin = 0.f;
#pragma unroll
    for (int k = 0; k < 16; k++) lin = fmaf(w1[k], pv[k], lin);

    float x2[6];
#pragma unroll
    for (int j = 0; j < 6; j++) {
        float a = 0.f;
#pragma unroll
        for (int k = 0; k < 16; k++) a = fmaf(w2[j * 16 + k], pv[k], a);
        x2[j] = a;
    }
    float quad = x2[0] * x2[3] + x2[1] * x2[4] + x2[2] * x2[5];
    out[b * TLEN + t] = lin + quad;
}

// ---------------- host launch ---------------------------------------------
extern "C" void kernel_launch(void* const* d_in, const int* in_sizes, int n_in,
                              void* d_out, int out_size) {
    const float* x       = (const float*)d_in[0];
    const float* conv1_w = (const float*)d_in[1];
    const float* res_w1  = (const float*)d_in[2];  // [10][64][32][3]
    const float* res_w2  = (const float*)d_in[3];  // [10][64][32]
    const float* post2_w = (const float*)d_in[4];
    const float* post3_w = (const float*)d_in[5];
    const float* post4_w = (const float*)d_in[6];
    const float* vnn1_w  = (const float*)d_in[7];
    const float* vnn2_w  = (const float*)d_in[8];
    float* out = (float*)d_out;

    float *h0p, *h1p, *tsp, *p2p, *p3p, *p4p;
    cudaGetSymbolAddress((void**)&h0p, g_h0);
    cudaGetSymbolAddress((void**)&h1p, g_h1);
    cudaGetSymbolAddress((void**)&tsp, g_ts);
    cudaGetSymbolAddress((void**)&p2p, g_p2);
    cudaGetSymbolAddress((void**)&p3p, g_p3);
    cudaGetSymbolAddress((void**)&p4p, g_p4);

    dim3 grid(TLEN / TT, BATCH);

    k_front<<<grid, TT>>>(x, conv1_w);

    const float* hin = h0p;
    float* hout = h1p;
    for (int s = 0; s < 2; s++) {
        for (int i = 0; i < 10; i++) {
            k_layer<<<grid, TT>>>(hin, hout,
                                  res_w1 + (size_t)i * 64 * 32 * 3,
                                  res_w2 + (size_t)i * 64 * 32,
                                  1 << i);
            const float* tmp = hout;
            hout = (float*)hin;
            hin = tmp;
        }
    }

    k_tanhskip<<<grid, TT>>>();
    k_conv3tanh<32, 16><<<grid, TT>>>(tsp, p2p, post2_w);
    k_conv3tanh<16, 8><<<grid, TT>>>(p2p, p3p, post3_w);
    k_conv3tanh<8, 1><<<grid, TT>>>(p3p, p4p, post4_w);
    k_vnn<<<grid, TT>>>(vnn1_w, vnn2_w, out);
}

// round 2
// speedup vs baseline: 1.2750x; 1.2750x over previous
#include <cuda_runtime.h>
#include <math.h>

#define TLEN  32000
#define BATCH 8
#define RES   32
#define SKIPC 32
#define TT    128   // threads per block; each thread handles 2 time samples

typedef unsigned long long ull;

// ---------------- f32x2 packed helpers (sm_103a FFMA2) ---------------------
__device__ __forceinline__ ull splat2(float v) {
    ull r;
    asm("mov.b64 %0, {%1, %1};" : "=l"(r) : "f"(v));
    return r;
}
__device__ __forceinline__ ull ffma2(ull a, ull b, ull c) {
    ull r;
    asm("fma.rn.f32x2 %0, %1, %2, %3;" : "=l"(r) : "l"(a), "l"(b), "l"(c));
    return r;
}
__device__ __forceinline__ float2 unpack2(ull r) {
    float2 f;
    asm("mov.b64 {%0, %1}, %2;" : "=f"(f.x), "=f"(f.y) : "l"(r));
    return f;
}

// overflow-safe fast tanh / sigmoid (rel err ~1e-6, budget is 1e-3)
__device__ __forceinline__ float ftanh(float x) {
    float e = __expf(-2.f * fabsf(x));
    float r = __fdividef(1.f - e, 1.f + e);
    return copysignf(r, x);
}
__device__ __forceinline__ float fsigm(float x) {
    return __fdividef(1.f, 1.f + __expf(-x));
}

// ---------------- device scratch (static; no allocations allowed) ----------
__device__ float g_h0[BATCH * RES * TLEN];
__device__ float g_h1[BATCH * RES * TLEN];
__device__ float g_skip[BATCH * SKIPC * TLEN];
__device__ float g_ts[BATCH * SKIPC * TLEN];
__device__ float g_p2[BATCH * 16 * TLEN];
__device__ float g_p3[BATCH * 8 * TLEN];
__device__ float g_p4[BATCH * 1 * TLEN];

// ---------------- front conv: x[B,1,T] -> h0[B,32,T]; also zero skip -------
__global__ __launch_bounds__(TT) void k_front(const float* __restrict__ x,
                                              const float* __restrict__ w) {
    int b = blockIdx.y;
    int t = blockIdx.x * TT + threadIdx.x;
    if (t >= TLEN) return;
    const float* xb = x + b * TLEN;
    float x0 = xb[t];
    float x1 = (t >= 1) ? xb[t - 1] : 0.f;
    float x2 = (t >= 2) ? xb[t - 2] : 0.f;
#pragma unroll
    for (int oc = 0; oc < RES; oc++) {
        float v = fmaf(w[oc * 3 + 0], x2,
                  fmaf(w[oc * 3 + 1], x1,
                       w[oc * 3 + 2] * x0));
        g_h0[(b * RES + oc) * TLEN + t] = v;
        g_skip[(b * SKIPC + oc) * TLEN + t] = 0.f;
    }
}

// ---------------- residual layer (f32x2 over oc-pairs, 2 samples/thread) ---
__global__ __launch_bounds__(TT) void k_layer(const float* __restrict__ hin,
                                              float* __restrict__ hout,
                                              const float* __restrict__ w1,  // [64][32][3]
                                              const float* __restrict__ w2,  // [64][32]
                                              int d) {
    __shared__ __align__(16) float w1s[3][RES][64];   // [k][ic][oc], oc contiguous
    __shared__ __align__(16) float w2s[RES][64];      // [ic][oc]

    int tid = threadIdx.x;
    for (int i = tid; i < 64 * RES * 3; i += TT) {
        int oc = i / 96, r = i % 96, ic = r / 3, k = r % 3;
        w1s[k][ic][oc] = w1[i];
    }
    for (int i = tid; i < 64 * RES; i += TT) {
        int oc = i / RES, ic = i % RES;
        w2s[ic][oc] = w2[i];
    }
    __syncthreads();

    int b = blockIdx.y;
    int t0 = blockIdx.x * (2 * TT) + tid;   // sample 0
    int t1 = t0 + TT;                       // sample 1 (always < TLEN: 125*256 grid)

    const float* hb = hin + b * RES * TLEN;

    // 64 oc as 32 packed pairs, for each of 2 samples
    ull a0[32], a1[32];
#pragma unroll
    for (int p = 0; p < 32; p++) { a0[p] = 0ULL; a1[p] = 0ULL; }

#pragma unroll
    for (int k = 0; k < 3; k++) {
        int off = (2 - k) * d;
        int tt0 = t0 - off;
        int tt1 = t1 - off;
#pragma unroll 4
        for (int ic = 0; ic < RES; ic++) {
            float v0 = (tt0 >= 0) ? hb[ic * TLEN + tt0] : 0.f;
            float v1 = (tt1 >= 0) ? hb[ic * TLEN + tt1] : 0.f;
            ull s0 = splat2(v0);
            ull s1 = splat2(v1);
            const ulonglong2* wp = reinterpret_cast<const ulonglong2*>(&w1s[k][ic][0]);
#pragma unroll
            for (int j = 0; j < 16; j++) {
                ulonglong2 w = wp[j];
                a0[2 * j]     = ffma2(s0, w.x, a0[2 * j]);
                a1[2 * j]     = ffma2(s1, w.x, a1[2 * j]);
                a0[2 * j + 1] = ffma2(s0, w.y, a0[2 * j + 1]);
                a1[2 * j + 1] = ffma2(s1, w.y, a1[2 * j + 1]);
            }
        }
    }

    // gating: g[c] = tanh(y[c]) * sigmoid(y[c+32]); pairs: y[2p,2p+1] in a[p]
    float g0[RES], g1[RES];
#pragma unroll
    for (int p = 0; p < 16; p++) {
        float2 ta = unpack2(a0[p]);
        float2 sa = unpack2(a0[p + 16]);
        g0[2 * p]     = ftanh(ta.x) * fsigm(sa.x);
        g0[2 * p + 1] = ftanh(ta.y) * fsigm(sa.y);
        float2 tb = unpack2(a1[p]);
        float2 sb = unpack2(a1[p + 16]);
        g1[2 * p]     = ftanh(tb.x) * fsigm(sb.x);
        g1[2 * p + 1] = ftanh(tb.y) * fsigm(sb.y);
    }

    float* hob = hout + b * RES * TLEN;
    float* skb = g_skip + b * SKIPC * TLEN;

    // 1x1 conv, residual half (oc 0..31)
    {
        ull z0[16], z1[16];
#pragma unroll
        for (int p = 0; p < 16; p++) { z0[p] = 0ULL; z1[p] = 0ULL; }
#pragma unroll 4
        for (int ic = 0; ic < RES; ic++) {
            ull s0 = splat2(g0[ic]);
            ull s1 = splat2(g1[ic]);
            const ulonglong2* wp = reinterpret_cast<const ulonglong2*>(&w2s[ic][0]);
#pragma unroll
            for (int j = 0; j < 8; j++) {
                ulonglong2 w = wp[j];
                z0[2 * j]     = ffma2(s0, w.x, z0[2 * j]);
                z1[2 * j]     = ffma2(s1, w.x, z1[2 * j]);
                z0[2 * j + 1] = ffma2(s0, w.y, z0[2 * j + 1]);
                z1[2 * j + 1] = ffma2(s1, w.y, z1[2 * j + 1]);
            }
        }
#pragma unroll
        for (int p = 0; p < 16; p++) {
            float2 f0 = unpack2(z0[p]);
            float2 f1 = unpack2(z1[p]);
            int c = 2 * p;
            hob[c * TLEN + t0]       = hb[c * TLEN + t0] + f0.x;
            hob[(c + 1) * TLEN + t0] = hb[(c + 1) * TLEN + t0] + f0.y;
            hob[c * TLEN + t1]       = hb[c * TLEN + t1] + f1.x;
            hob[(c + 1) * TLEN + t1] = hb[(c + 1) * TLEN + t1] + f1.y;
        }
    }

    // 1x1 conv, skip half (oc 32..63)
    {
        ull z0[16], z1[16];
#pragma unroll
        for (int p = 0; p < 16; p++) { z0[p] = 0ULL; z1[p] = 0ULL; }
#pragma unroll 4
        for (int ic = 0; ic < RES; ic++) {
            ull s0 = splat2(g0[ic]);
            ull s1 = splat2(g1[ic]);
            const ulonglong2* wp = reinterpret_cast<const ulonglong2*>(&w2s[ic][32]);
#pragma unroll
            for (int j = 0; j < 8; j++) {
                ulonglong2 w = wp[j];
                z0[2 * j]     = ffma2(s0, w.x, z0[2 * j]);
                z1[2 * j]     = ffma2(s1, w.x, z1[2 * j]);
                z0[2 * j + 1] = ffma2(s0, w.y, z0[2 * j + 1]);
                z1[2 * j + 1] = ffma2(s1, w.y, z1[2 * j + 1]);
            }
        }
#pragma unroll
        for (int p = 0; p < 16; p++) {
            float2 f0 = unpack2(z0[p]);
            float2 f1 = unpack2(z1[p]);
            int c = 2 * p;
            skb[c * TLEN + t0]       += f0.x;
            skb[(c + 1) * TLEN + t0] += f0.y;
            skb[c * TLEN + t1]       += f1.x;
            skb[(c + 1) * TLEN + t1] += f1.y;
        }
    }
}

// ---------------- tanh over skip ------------------------------------------
__global__ __launch_bounds__(TT) void k_tanhskip() {
    int b = blockIdx.y;
    int t = blockIdx.x * TT + threadIdx.x;
    if (t >= TLEN) return;
#pragma unroll
    for (int c = 0; c < SKIPC; c++) {
        int idx = (b * SKIPC + c) * TLEN + t;
        g_ts[idx] = ftanh(g_skip[idx]);
    }
}

// ---------------- generic causal k=3 conv + tanh --------------------------
template <int IC, int OC>
__global__ __launch_bounds__(TT) void k_conv3tanh(const float* __restrict__ in,
                                                  float* __restrict__ out,
                                                  const float* __restrict__ w) {
    __shared__ float ws[3][IC][OC];
    int tid = threadIdx.x;
    for (int i = tid; i < OC * IC * 3; i += TT) {
        int oc = i / (IC * 3), r = i % (IC * 3), ic = r / 3, k = r % 3;
        ws[k][ic][oc] = w[i];
    }
    __syncthreads();

    int b = blockIdx.y;
    int t = blockIdx.x * TT + tid;
    if (t >= TLEN) return;
    const float* ib = in + b * IC * TLEN;

    float acc[OC];
#pragma unroll
    for (int o = 0; o < OC; o++) acc[o] = 0.f;

#pragma unroll
    for (int k = 0; k < 3; k++) {
        int tt = t - (2 - k);
        if (tt >= 0) {
#pragma unroll
            for (int ic = 0; ic < IC; ic++) {
                float v = ib[ic * TLEN + tt];
#pragma unroll
                for (int o = 0; o < OC; o++)
                    acc[o] = fmaf(v, ws[k][ic][o], acc[o]);
            }
        }
    }
    float* ob = out + b * OC * TLEN;
#pragma unroll
    for (int o = 0; o < OC; o++)
        ob[o * TLEN + t] = ftanh(acc[o]);
}

// ---------------- Volterra head -------------------------------------------
__global__ __launch_bounds__(TT) void k_vnn(const float* __restrict__ w1,   // [16]
                                            const float* __restrict__ w2,   // [6][16]
                                            float* __restrict__ out) {
    int b = blockIdx.y;
    int t = blockIdx.x * TT + threadIdx.x;
    if (t >= TLEN) return;
    const float* pb = g_p4 + b * TLEN;

    float pv[16];
#pragma unroll
    for (int k = 0; k < 16; k++) {
        int tt = t - (15 - k);
        pv[k] = (tt >= 0) ? pb[tt] : 0.f;
    }
    float lin = 0.f;
#pragma unroll
    for (int k = 0; k < 16; k++) lin = fmaf(w1[k], pv[k], lin);

    float x2[6];
#pragma unroll
    for (int j = 0; j < 6; j++) {
        float a = 0.f;
#pragma unroll
        for (int k = 0; k < 16; k++) a = fmaf(w2[j * 16 + k], pv[k], a);
        x2[j] = a;
    }
    float quad = x2[0] * x2[3] + x2[1] * x2[4] + x2[2] * x2[5];
    out[b * TLEN + t] = lin + quad;
}

// ---------------- host launch ---------------------------------------------
extern "C" void kernel_launch(void* const* d_in, const int* in_sizes, int n_in,
                              void* d_out, int out_size) {
    const float* x       = (const float*)d_in[0];
    const float* conv1_w = (const float*)d_in[1];
    const float* res_w1  = (const float*)d_in[2];  // [10][64][32][3]
    const float* res_w2  = (const float*)d_in[3];  // [10][64][32]
    const float* post2_w = (const float*)d_in[4];
    const float* post3_w = (const float*)d_in[5];
    const float* post4_w = (const float*)d_in[6];
    const float* vnn1_w  = (const float*)d_in[7];
    const float* vnn2_w  = (const float*)d_in[8];
    float* out = (float*)d_out;

    float *h0p, *h1p, *tsp, *p2p, *p3p, *p4p;
    cudaGetSymbolAddress((void**)&h0p, g_h0);
    cudaGetSymbolAddress((void**)&h1p, g_h1);
    cudaGetSymbolAddress((void**)&tsp, g_ts);
    cudaGetSymbolAddress((void**)&p2p, g_p2);
    cudaGetSymbolAddress((void**)&p3p, g_p3);
    cudaGetSymbolAddress((void**)&p4p, g_p4);

    dim3 grid1(TLEN / TT, BATCH);          // 250 x 8, one sample/thread
    dim3 grid2(TLEN / (2 * TT), BATCH);    // 125 x 8, two samples/thread

    k_front<<<grid1, TT>>>(x, conv1_w);

    const float* hin = h0p;
    float* hout = h1p;
    for (int s = 0; s < 2; s++) {
        for (int i = 0; i < 10; i++) {
            k_layer<<<grid2, TT>>>(hin, hout,
                                   res_w1 + (size_t)i * 64 * 32 * 3,
                                   res_w2 + (size_t)i * 64 * 32,
                                   1 << i);
            const float* tmp = hout;
            hout = (float*)hin;
            hin = tmp;
        }
    }

    k_tanhskip<<<grid1, TT>>>();
    k_conv3tanh<32, 16><<<grid1, TT>>>(tsp, p2p, post2_w);
    k_conv3tanh<16, 8><<<grid1, TT>>>(p2p, p3p, post3_w);
    k_conv3tanh<8, 1><<<grid1, TT>>>(p3p, p4p, post4_w);
    k_vnn<<<grid1, TT>>>(vnn1_w, vnn2_w, out);
}

// round 4
// speedup vs baseline: 2.1081x; 1.6534x over previous
#include <cuda_runtime.h>
#include <math.h>
#include <stdint.h>

#define TLEN  32000
#define BATCH 8
#define RES   32
#define SKIPC 32
#define TT    128

typedef unsigned long long ull;

// ==================== helpers ==============================================
__device__ __forceinline__ uint32_t smem_u32(const void* p) {
    uint32_t a;
    asm("{ .reg .u64 t; cvta.to.shared.u64 t, %1; cvt.u32.u64 %0, t; }" : "=r"(a) : "l"(p));
    return a;
}
__device__ __forceinline__ uint32_t lds32(uint32_t a) {
    uint32_t v;
    asm volatile("ld.shared.b32 %0, [%1];" : "=r"(v) : "r"(a));
    return v;
}
__device__ __forceinline__ void sts32(uint32_t a, uint32_t v) {
    asm volatile("st.shared.b32 [%0], %1;" :: "r"(a), "r"(v));
}
// pack {lo=v0, hi=v1} as bf16x2 (RN)
__device__ __forceinline__ uint32_t pack_bf16x2(float v0, float v1) {
    uint32_t r;
    asm("cvt.rn.bf16x2.f32 %0, %1, %2;" : "=r"(r) : "f"(v1), "f"(v0));
    return r;
}
// mma.sync m16n8k16 bf16, fp32 accumulate
__device__ __forceinline__ void mma_bf16(float* c,
                                         uint32_t a0, uint32_t a1, uint32_t a2, uint32_t a3,
                                         uint32_t b0, uint32_t b1) {
    asm volatile("mma.sync.aligned.m16n8k16.row.col.f32.bf16.bf16.f32 "
                 "{%0,%1,%2,%3}, {%4,%5,%6,%7}, {%8,%9}, {%0,%1,%2,%3};"
                 : "+f"(c[0]), "+f"(c[1]), "+f"(c[2]), "+f"(c[3])
                 : "r"(a0), "r"(a1), "r"(a2), "r"(a3), "r"(b0), "r"(b1));
}
__device__ __forceinline__ float ftanh(float x) {
    float e = __expf(-2.f * fabsf(x));
    float r = __fdividef(1.f - e, 1.f + e);
    return copysignf(r, x);
}
__device__ __forceinline__ float fsigm(float x) {
    return __fdividef(1.f, 1.f + __expf(-x));
}
// split pair into bf16 hi pack + residual lo pack
__device__ __forceinline__ void split_pair(float v0, float v1, uint32_t& hi, uint32_t& lo) {
    hi = pack_bf16x2(v0, v1);
    float h0 = __uint_as_float((hi & 0xFFFFu) << 16);
    float h1 = __uint_as_float(hi & 0xFFFF0000u);
    lo = pack_bf16x2(v0 - h0, v1 - h1);
}

// ==================== device scratch =======================================
__device__ float g_h0[BATCH * RES * TLEN];
__device__ float g_h1[BATCH * RES * TLEN];
__device__ float g_skip[BATCH * SKIPC * TLEN];
__device__ float g_ts[BATCH * SKIPC * TLEN];
__device__ float g_p2[BATCH * 16 * TLEN];
__device__ float g_p3[BATCH * 8 * TLEN];
__device__ float g_p4[BATCH * 1 * TLEN];

// ==================== front conv ===========================================
__global__ __launch_bounds__(TT) void k_front(const float* __restrict__ x,
                                              const float* __restrict__ w) {
    int b = blockIdx.y;
    int t = blockIdx.x * TT + threadIdx.x;
    if (t >= TLEN) return;
    const float* xb = x + b * TLEN;
    float x0 = xb[t];
    float x1 = (t >= 1) ? xb[t - 1] : 0.f;
    float x2 = (t >= 2) ? xb[t - 2] : 0.f;
#pragma unroll
    for (int oc = 0; oc < RES; oc++) {
        float v = fmaf(w[oc * 3 + 0], x2, fmaf(w[oc * 3 + 1], x1, w[oc * 3 + 2] * x0));
        g_h0[(b * RES + oc) * TLEN + t] = v;
        g_skip[(b * SKIPC + oc) * TLEN + t] = 0.f;
    }
}

// ==================== residual layer via mma.sync bf16 =====================
// SMEM layout (byte offsets, bf16 elements, padded strides)
#define STRA 200   // A/B row stride bytes (100 bf16)
#define STRG 72    // G/W2 row stride bytes (36 bf16)
#define SO_AH 0
#define SO_AL (SO_AH + 128 * STRA)        // 25600
#define SO_BH (SO_AL + 128 * STRA)        // 51200
#define SO_BL (SO_BH + 64 * STRA)         // 64000
#define SO_GH (SO_BL + 64 * STRA)         // 76800
#define SO_GL (SO_GH + 128 * STRG)        // 86016
#define SO_W2H (SO_GL + 128 * STRG)       // 95232
#define SO_W2L (SO_W2H + 64 * STRG)       // 99840
#define SMEM_LAYER_BYTES (SO_W2L + 64 * STRG)  // 104448

// one GEMM pass: D[128x64] += A[128xK]·B[64xK]^T, K = nk16*16
__device__ __forceinline__ void gemm_pass(uint32_t aB, uint32_t bB, int stride,
                                          int nk16, float acc[2][8][4],
                                          int wid, int qr, int qc) {
    uint32_t aRow = aB + (uint32_t)((32 * wid + qr) * stride + qc * 4);
    for (int k = 0; k < nk16; k++) {
        uint32_t ka = (uint32_t)(k * 32);
        uint32_t a00 = lds32(aRow + ka);
        uint32_t a01 = lds32(aRow + 8 * stride + ka);
        uint32_t a02 = lds32(aRow + ka + 16);
        uint32_t a03 = lds32(aRow + 8 * stride + ka + 16);
        uint32_t a10 = lds32(aRow + 16 * stride + ka);
        uint32_t a11 = lds32(aRow + 24 * stride + ka);
        uint32_t a12 = lds32(aRow + 16 * stride + ka + 16);
        uint32_t a13 = lds32(aRow + 24 * stride + ka + 16);
#pragma unroll
        for (int n = 0; n < 8; n++) {
            uint32_t bAddr = bB + (uint32_t)((8 * n + qr) * stride + qc * 4) + ka;
            uint32_t b0 = lds32(bAddr);
            uint32_t b1 = lds32(bAddr + 16);
            mma_bf16(acc[0][n], a00, a01, a02, a03, b0, b1);
            mma_bf16(acc[1][n], a10, a11, a12, a13, b0, b1);
        }
    }
}

__global__ __launch_bounds__(TT, 2) void k_layer(const float* __restrict__ hin,
                                                 float* __restrict__ hout,
                                                 const float* __restrict__ w1,  // [64][32][3]
                                                 const float* __restrict__ w2,  // [64][32]
                                                 int d) {
    extern __shared__ __align__(16) char smem[];
    uint32_t sb = smem_u32(smem);
    int tid = threadIdx.x;
    int wid = tid >> 5;
    int lid = tid & 31;
    int qr = lid >> 2;   // 0..7
    int qc = lid & 3;    // 0..3
    int b = blockIdx.y;
    int t0 = blockIdx.x * TT;

    const float* hb = hin + b * RES * TLEN;

    // ---- stage A [128][96] hi/lo: thread = time row m
    {
        int m = tid;
        int t = t0 + m;
        uint32_t rowH = sb + SO_AH + (uint32_t)(m * STRA);
        uint32_t rowL = sb + SO_AL + (uint32_t)(m * STRA);
#pragma unroll
        for (int tap = 0; tap < 3; tap++) {
            int tt = t - (2 - tap) * d;
            bool ok = (tt >= 0);
#pragma unroll
            for (int ic = 0; ic < 32; ic += 2) {
                float v0 = ok ? hb[ic * TLEN + tt] : 0.f;
                float v1 = ok ? hb[(ic + 1) * TLEN + tt] : 0.f;
                uint32_t hi, lo;
                split_pair(v0, v1, hi, lo);
                uint32_t off = (uint32_t)((tap * 32 + ic) * 2);
                sts32(rowH + off, hi);
                sts32(rowL + off, lo);
            }
        }
    }
    // ---- stage B (w1) [64][96] hi/lo: pairs
    for (int i = tid; i < 64 * 48; i += TT) {
        int oc = i / 48, pj = i % 48;
        int k0 = 2 * pj;
        int tap = k0 >> 5, ic = k0 & 31;
        float v0 = w1[oc * 96 + ic * 3 + tap];
        float v1 = w1[oc * 96 + (ic + 1) * 3 + tap];
        uint32_t hi, lo;
        split_pair(v0, v1, hi, lo);
        uint32_t off = (uint32_t)(oc * STRA + k0 * 2);
        sts32(sb + SO_BH + off, hi);
        sts32(sb + SO_BL + off, lo);
    }
    // ---- stage W2 [64][32] hi/lo
    for (int i = tid; i < 64 * 16; i += TT) {
        int oc = i / 16, ic = 2 * (i % 16);
        float v0 = w2[oc * 32 + ic];
        float v1 = w2[oc * 32 + ic + 1];
        uint32_t hi, lo;
        split_pair(v0, v1, hi, lo);
        uint32_t off = (uint32_t)(oc * STRG + ic * 2);
        sts32(sb + SO_W2H + off, hi);
        sts32(sb + SO_W2L + off, lo);
    }
    __syncthreads();

    // ---- conv GEMM: 3 passes (AH·BH, AL·BH, AH·BL)
    float acc[2][8][4];
#pragma unroll
    for (int m = 0; m < 2; m++)
#pragma unroll
        for (int n = 0; n < 8; n++)
#pragma unroll
            for (int j = 0; j < 4; j++) acc[m][n][j] = 0.f;

    gemm_pass(sb + SO_AH, sb + SO_BH, STRA, 6, acc, wid, qr, qc);
    gemm_pass(sb + SO_AL, sb + SO_BH, STRA, 6, acc, wid, qr, qc);
    gemm_pass(sb + SO_AH, sb + SO_BL, STRA, 6, acc, wid, qr, qc);

    // ---- gating -> G [128][32] hi/lo in SMEM
#pragma unroll
    for (int m = 0; m < 2; m++) {
#pragma unroll
        for (int rh = 0; rh < 2; rh++) {
            int row = 32 * wid + 16 * m + qr + 8 * rh;
            uint32_t goff = (uint32_t)(row * STRG + (2 * qc) * 2);
#pragma unroll
            for (int n = 0; n < 4; n++) {
                float g0 = ftanh(acc[m][n][2 * rh + 0]) * fsigm(acc[m][n + 4][2 * rh + 0]);
                float g1 = ftanh(acc[m][n][2 * rh + 1]) * fsigm(acc[m][n + 4][2 * rh + 1]);
                uint32_t hi, lo;
                split_pair(g0, g1, hi, lo);
                sts32(sb + SO_GH + goff + (uint32_t)(n * 16), hi);
                sts32(sb + SO_GL + goff + (uint32_t)(n * 16), lo);
            }
        }
    }
    __syncthreads();

    // ---- 1x1 GEMM: z[128x64] = G[128x32]·W2[64x32]^T, 3 passes
    float acc2[2][8][4];
#pragma unroll
    for (int m = 0; m < 2; m++)
#pragma unroll
        for (int n = 0; n < 8; n++)
#pragma unroll
            for (int j = 0; j < 4; j++) acc2[m][n][j] = 0.f;

    gemm_pass(sb + SO_GH, sb + SO_W2H, STRG, 2, acc2, wid, qr, qc);
    gemm_pass(sb + SO_GL, sb + SO_W2H, STRG, 2, acc2, wid, qr, qc);
    gemm_pass(sb + SO_GH, sb + SO_W2L, STRG, 2, acc2, wid, qr, qc);

    // ---- epilogue: residual + skip
    float* hob = hout + b * RES * TLEN;
    float* skb = g_skip + b * SKIPC * TLEN;
#pragma unroll
    for (int m = 0; m < 2; m++) {
#pragma unroll
        for (int rh = 0; rh < 2; rh++) {
            int t = t0 + 32 * wid + 16 * m + qr + 8 * rh;
#pragma unroll
            for (int n = 0; n < 4; n++) {
                int c = 8 * n + 2 * qc;
                hob[c * TLEN + t]       = hb[c * TLEN + t] + acc2[m][n][2 * rh + 0];
                hob[(c + 1) * TLEN + t] = hb[(c + 1) * TLEN + t] + acc2[m][n][2 * rh + 1];
            }
#pragma unroll
            for (int n = 4; n < 8; n++) {
                int c = 8 * (n - 4) + 2 * qc;
                skb[c * TLEN + t]       += acc2[m][n][2 * rh + 0];
                skb[(c + 1) * TLEN + t] += acc2[m][n][2 * rh + 1];
            }
        }
    }
}

// ==================== tanh over skip =======================================
__global__ __launch_bounds__(TT) void k_tanhskip() {
    int b = blockIdx.y;
    int t = blockIdx.x * TT + threadIdx.x;
    if (t >= TLEN) return;
#pragma unroll
    for (int c = 0; c < SKIPC; c++) {
        int idx = (b * SKIPC + c) * TLEN + t;
        g_ts[idx] = ftanh(g_skip[idx]);
    }
}

// ==================== generic causal k=3 conv + tanh =======================
template <int IC, int OC>
__global__ __launch_bounds__(TT) void k_conv3tanh(const float* __restrict__ in,
                                                  float* __restrict__ out,
                                                  const float* __restrict__ w) {
    __shared__ float ws[3][IC][OC];
    int tid = threadIdx.x;
    for (int i = tid; i < OC * IC * 3; i += TT) {
        int oc = i / (IC * 3), r = i % (IC * 3), ic = r / 3, k = r % 3;
        ws[k][ic][oc] = w[i];
    }
    __syncthreads();

    int b = blockIdx.y;
    int t = blockIdx.x * TT + tid;
    if (t >= TLEN) return;
    const float* ib = in + b * IC * TLEN;

    float acc[OC];
#pragma unroll
    for (int o = 0; o < OC; o++) acc[o] = 0.f;
#pragma unroll
    for (int k = 0; k < 3; k++) {
        int tt = t - (2 - k);
        if (tt >= 0) {
#pragma unroll
            for (int ic = 0; ic < IC; ic++) {
                float v = ib[ic * TLEN + tt];
#pragma unroll
                for (int o = 0; o < OC; o++)
                    acc[o] = fmaf(v, ws[k][ic][o], acc[o]);
            }
        }
    }
    float* ob = out + b * OC * TLEN;
#pragma unroll
    for (int o = 0; o < OC; o++)
        ob[o * TLEN + t] = ftanh(acc[o]);
}

// ==================== Volterra head ========================================
__global__ __launch_bounds__(TT) void k_vnn(const float* __restrict__ w1,
                                            const float* __restrict__ w2,
                                            float* __restrict__ out) {
    int b = blockIdx.y;
    int t = blockIdx.x * TT + threadIdx.x;
    if (t >= TLEN) return;
    const float* pb = g_p4 + b * TLEN;

    float pv[16];
#pragma unroll
    for (int k = 0; k < 16; k++) {
        int tt = t - (15 - k);
        pv[k] = (tt >= 0) ? pb[tt] : 0.f;
    }
    float lin = 0.f;
#pragma unroll
    for (int k = 0; k < 16; k++) lin = fmaf(w1[k], pv[k], lin);

    float x2[6];
#pragma unroll
    for (int j = 0; j < 6; j++) {
        float a = 0.f;
#pragma unroll
        for (int k = 0; k < 16; k++) a = fmaf(w2[j * 16 + k], pv[k], a);
        x2[j] = a;
    }
    float quad = x2[0] * x2[3] + x2[1] * x2[4] + x2[2] * x2[5];
    out[b * TLEN + t] = lin + quad;
}

// ==================== host launch ==========================================
extern "C" void kernel_launch(void* const* d_in, const int* in_sizes, int n_in,
                              void* d_out, int out_size) {
    const float* x       = (const float*)d_in[0];
    const float* conv1_w = (const float*)d_in[1];
    const float* res_w1  = (const float*)d_in[2];
    const float* res_w2  = (const float*)d_in[3];
    const float* post2_w = (const float*)d_in[4];
    const float* post3_w = (const float*)d_in[5];
    const float* post4_w = (const float*)d_in[6];
    const float* vnn1_w  = (const float*)d_in[7];
    const float* vnn2_w  = (const float*)d_in[8];
    float* out = (float*)d_out;

    float *h0p, *h1p, *tsp, *p2p, *p3p, *p4p;
    cudaGetSymbolAddress((void**)&h0p, g_h0);
    cudaGetSymbolAddress((void**)&h1p, g_h1);
    cudaGetSymbolAddress((void**)&tsp, g_ts);
    cudaGetSymbolAddress((void**)&p2p, g_p2);
    cudaGetSymbolAddress((void**)&p3p, g_p3);
    cudaGetSymbolAddress((void**)&p4p, g_p4);

    cudaFuncSetAttribute(k_layer, cudaFuncAttributeMaxDynamicSharedMemorySize,
                         SMEM_LAYER_BYTES);

    dim3 grid(TLEN / TT, BATCH);   // 250 x 8

    k_front<<<grid, TT>>>(x, conv1_w);

    const float* hin = h0p;
    float* hout = h1p;
    for (int s = 0; s < 2; s++) {
        for (int i = 0; i < 10; i++) {
            k_layer<<<grid, TT, SMEM_LAYER_BYTES>>>(hin, hout,
                                                    res_w1 + (size_t)i * 64 * 32 * 3,
                                                    res_w2 + (size_t)i * 64 * 32,
                                                    1 << i);
            const float* tmp = hout;
            hout = (float*)hin;
            hin = tmp;
        }
    }

    k_tanhskip<<<grid, TT>>>();
    k_conv3tanh<32, 16><<<grid, TT>>>(tsp, p2p, post2_w);
    k_conv3tanh<16, 8><<<grid, TT>>>(p2p, p3p, post3_w);
    k_conv3tanh<8, 1><<<grid, TT>>>(p3p, p4p, post4_w);
    k_vnn<<<grid, TT>>>(vnn1_w, vnn2_w, out);
}